// round 2
// baseline (speedup 1.0000x reference)
#include <cuda_runtime.h>
#include <cstdint>
#include <math.h>

#define B_  2
#define T_  2048
#define D_  2048
#define H_  32
#define HD_ 64
#define KW  (D_/4)   // 512 int words per D row

// ---------------- scratch (no allocation allowed) ----------------
static __device__ int g_mode;   // 0 = packed int8, 1 = int32-per-elem, 2 = float32-per-elem
static __device__ __align__(16) int8_t g_hs[B_*T_*D_];
static __device__ __align__(16) int8_t g_Wq[D_*D_];
static __device__ __align__(16) int8_t g_Wk[D_*D_];
static __device__ __align__(16) int8_t g_Wv[D_*D_];
static __device__ __align__(16) int8_t g_Wo[D_*D_];
static __device__ __align__(16) int8_t g_bq[D_];
static __device__ __align__(16) int8_t g_bk[D_];
static __device__ __align__(16) int8_t g_bv[D_];
static __device__ __align__(16) int8_t g_q [B_*T_*D_];
static __device__ __align__(16) int8_t g_k [B_*T_*D_];
static __device__ __align__(16) int8_t g_v [B_*T_*D_];
static __device__ __align__(16) int8_t g_ao[B_*T_*D_];

// ---------------- dtype sniff: deterministic, runs on hidden_states ----------------
__global__ void sniff_kernel(const void* __restrict__ p)
{
    __shared__ int s_i32, s_f32;
    if (threadIdx.x == 0) { s_i32 = 1; s_f32 = 1; }
    __syncthreads();
    const int*   wi = (const int*)p;
    const float* wf = (const float*)p;
    int ok_i = 1, ok_f = 1;
    for (int i = threadIdx.x; i < 4096; i += blockDim.x) {
        int v = wi[i];
        if (v < -128 || v > 127) ok_i = 0;
        float f = wf[i];
        if (!(f >= -128.f && f <= 127.f && f == rintf(f))) ok_f = 0;
    }
    if (!ok_i) atomicExch(&s_i32, 0);
    if (!ok_f) atomicExch(&s_f32, 0);
    __syncthreads();
    if (threadIdx.x == 0) g_mode = s_i32 ? 1 : (s_f32 ? 2 : 0);
}

// ---------------- pack: normalize a logically-int8 input into packed int8 ----------------
// sel: 0=hs 1=Wq 2=Wk 3=Wv 4=Wo 5=bq 6=bk 7=bv
__global__ void pack_kernel(const void* __restrict__ in, int nwords, int sel)
{
    int8_t* outp =
        (sel == 0) ? g_hs : (sel == 1) ? g_Wq : (sel == 2) ? g_Wk :
        (sel == 3) ? g_Wv : (sel == 4) ? g_Wo : (sel == 5) ? g_bq :
        (sel == 6) ? g_bk : g_bv;
    int* ow = (int*)outp;
    const int mode = g_mode;
    int i = blockIdx.x * blockDim.x + threadIdx.x;
    const int stride = gridDim.x * blockDim.x;
    for (; i < nwords; i += stride) {
        int w;
        if (mode == 0) {
            w = ((const int*)in)[i];
        } else if (mode == 1) {
            int4 v = ((const int4*)in)[i];
            w = (v.x & 255) | ((v.y & 255) << 8) | ((v.z & 255) << 16) | ((v.w & 255) << 24);
        } else {
            float4 v = ((const float4*)in)[i];
            int a = (int)rintf(v.x) & 255, b = (int)rintf(v.y) & 255;
            int c = (int)rintf(v.z) & 255, d = (int)rintf(v.w) & 255;
            w = a | (b << 8) | (c << 16) | (d << 24);
        }
        ow[i] = w;
    }
}

// ---------------- int8 GEMM: Y[m,n] = epilogue( sum_k X[m,k]*W[n,k] ) ----------------
// sel 0/1/2: X=g_hs, W=g_Wq/Wk/Wv, int8 bias, int8 out to g_q/g_k/g_v (W8A8B8O8)
// sel 3    : X=g_ao, W=g_Wo, fp32 bias param, fp32 out (W8A8BFP32OFP32)
__global__ __launch_bounds__(256) void gemm_i8_kernel(
    const float* __restrict__ bias_f, float alpha, float* __restrict__ outf, int sel)
{
    const int N = D_;
    const int* Xw = (sel == 3) ? (const int*)g_ao : (const int*)g_hs;
    const int* Ww = (sel == 0) ? (const int*)g_Wq : (sel == 1) ? (const int*)g_Wk
                  : (sel == 2) ? (const int*)g_Wv : (const int*)g_Wo;
    const int8_t* bias_i8 = (sel == 0) ? g_bq : (sel == 1) ? g_bk : g_bv;

    __shared__ int As[64][17];
    __shared__ int Bs[64][17];

    const int tid = threadIdx.x;
    const int tx = tid & 15, ty = tid >> 4;
    const int m0 = blockIdx.y * 64, n0 = blockIdx.x * 64;

    int acc[4][4];
    #pragma unroll
    for (int i = 0; i < 4; i++)
        #pragma unroll
        for (int j = 0; j < 4; j++) acc[i][j] = 0;

    for (int kt = 0; kt < KW; kt += 16) {
        #pragma unroll
        for (int l = 0; l < 4; ++l) {
            int idx = tid + l * 256;
            int r = idx >> 4, c = idx & 15;
            As[r][c] = Xw[(size_t)(m0 + r) * KW + kt + c];
            Bs[r][c] = Ww[(size_t)(n0 + r) * KW + kt + c];
        }
        __syncthreads();
        #pragma unroll
        for (int w = 0; w < 16; ++w) {
            int a[4], b[4];
            #pragma unroll
            for (int i = 0; i < 4; i++) a[i] = As[ty + 16 * i][w];
            #pragma unroll
            for (int j = 0; j < 4; j++) b[j] = Bs[tx + 16 * j][w];
            #pragma unroll
            for (int i = 0; i < 4; i++)
                #pragma unroll
                for (int j = 0; j < 4; j++)
                    acc[i][j] = __dp4a(a[i], b[j], acc[i][j]);
        }
        __syncthreads();
    }

    if (sel < 3) {
        int8_t* Y = (sel == 0) ? g_q : (sel == 1) ? g_k : g_v;
        #pragma unroll
        for (int i = 0; i < 4; i++) {
            int m = m0 + ty + 16 * i;
            #pragma unroll
            for (int j = 0; j < 4; j++) {
                int n = n0 + tx + 16 * j;
                float y = __fadd_rn(__fmul_rn(alpha, (float)acc[i][j]),
                                    (float)bias_i8[n]);
                int q = (int)rintf(y);
                q = max(-128, min(127, q));
                Y[(size_t)m * N + n] = (int8_t)q;
            }
        }
    } else {
        #pragma unroll
        for (int i = 0; i < 4; i++) {
            int m = m0 + ty + 16 * i;
            #pragma unroll
            for (int j = 0; j < 4; j++) {
                int n = n0 + tx + 16 * j;
                outf[(size_t)m * N + n] =
                    __fadd_rn(__fmul_rn(alpha, (float)acc[i][j]), bias_f[n]);
            }
        }
    }
}

// ---------------- fused attention: QK^T -> softmax -> quant -> PV -> int8 ----------------
__global__ __launch_bounds__(256) void attn_kernel()
{
    const float A_QK = 2e-5f, A_PV = 1e-2f;
    const int bh = blockIdx.y;
    const int b = bh >> 5, h = bh & 31;
    const int r0 = blockIdx.x * 64;
    const int tid = threadIdx.x;
    const int row = tid & 63, sub = tid >> 6;
    const int t = r0 + row;

    __shared__ int   qs[64][17];
    __shared__ int   ks[128][17];
    __shared__ int   vraw[128][17];
    __shared__ int   vT[64][33];   // vT[d][sw] packs v[s0+4sw .. +3][d]
    __shared__ int   ps[64][33];   // ps[row][sw] packs p_i8[s0+4sw .. +3]
    __shared__ float red[64][4][2];
    __shared__ float rowM[64], rowL[64];

    const int* Qw = (const int*)g_q;
    const int* Kw = (const int*)g_k;
    const int* Vw = (const int*)g_v;

    #pragma unroll
    for (int l = 0; l < 4; ++l) {
        int idx = tid + l * 256;
        int r = idx >> 4, c = idx & 15;
        qs[r][c] = Qw[(size_t)(b * T_ + r0 + r) * KW + h * 16 + c];
    }

    const int nch = ((r0 + 63) >> 7) + 1;

    // ---- pass A: online max / sum of exp ----
    float m = -INFINITY, lsum = 0.f;
    for (int c = 0; c < nch; ++c) {
        const int s0 = c << 7;
        #pragma unroll
        for (int lo = 0; lo < 8; ++lo) {
            int idx = tid + lo * 256;
            int r = idx >> 4, w = idx & 15;
            ks[r][w] = Kw[(size_t)(b * T_ + s0 + r) * KW + h * 16 + w];
        }
        __syncthreads();
        int smax = t - s0 + 1; if (smax > 128) smax = 128;
        const int lo_ = sub * 32;
        const int hi_ = min(sub * 32 + 32, smax);
        for (int sl = lo_; sl < hi_; ++sl) {
            int d = 0;
            #pragma unroll
            for (int w = 0; w < 16; ++w) d = __dp4a(qs[row][w], ks[sl][w], d);
            float sc = __fmul_rn(A_QK, (float)d);
            float mn = fmaxf(m, sc);
            lsum = lsum * expf(m - mn) + expf(sc - mn);
            m = mn;
        }
        __syncthreads();
    }
    red[row][sub][0] = m;
    red[row][sub][1] = lsum;
    __syncthreads();
    if (sub == 0) {
        float M = red[row][0][0];
        #pragma unroll
        for (int i = 1; i < 4; i++) M = fmaxf(M, red[row][i][0]);
        float L = 0.f;
        #pragma unroll
        for (int i = 0; i < 4; i++) L += red[row][i][1] * expf(red[row][i][0] - M);
        rowM[row] = M; rowL[row] = L;
    }
    __syncthreads();

    const float M = rowM[row], L = rowL[row];

    // ---- pass B: recompute scores, quantize, PV ----
    int acc[16];
    #pragma unroll
    for (int i = 0; i < 16; i++) acc[i] = 0;

    for (int c = 0; c < nch; ++c) {
        const int s0 = c << 7;
        #pragma unroll
        for (int lo = 0; lo < 8; ++lo) {
            int idx = tid + lo * 256;
            int r = idx >> 4, w = idx & 15;
            size_t base = (size_t)(b * T_ + s0 + r) * KW + h * 16 + w;
            ks[r][w]   = Kw[base];
            vraw[r][w] = Vw[base];
        }
        __syncthreads();

        #pragma unroll
        for (int g = 0; g < 8; ++g) {
            unsigned word = 0;
            #pragma unroll
            for (int z = 0; z < 4; ++z) {
                int sl = sub * 32 + g * 4 + z;
                int s  = s0 + sl;
                int pq = 0;
                if (s <= t) {
                    int d = 0;
                    #pragma unroll
                    for (int w = 0; w < 16; ++w) d = __dp4a(qs[row][w], ks[sl][w], d);
                    float sc = __fmul_rn(A_QK, (float)d);
                    float p  = expf(sc - M) / L;
                    pq = (int)rintf(__fmul_rn(p, 127.f));
                    pq = max(0, min(127, pq));
                }
                word |= ((unsigned)pq & 255u) << (8 * z);
            }
            ps[row][sub * 8 + g] = (int)word;
        }

        #pragma unroll
        for (int k = 0; k < 8; ++k) {
            int idx = tid * 8 + k;
            int d = idx >> 5, sw = idx & 31;
            unsigned word = 0;
            #pragma unroll
            for (int z = 0; z < 4; ++z) {
                unsigned by = ((unsigned)vraw[4 * sw + z][d >> 2] >> ((d & 3) * 8)) & 255u;
                word |= by << (8 * z);
            }
            vT[d][sw] = (int)word;
        }
        __syncthreads();

        int pr[32];
        #pragma unroll
        for (int sw = 0; sw < 32; ++sw) pr[sw] = ps[row][sw];
        const int dbase = sub * 16;
        #pragma unroll
        for (int i = 0; i < 16; ++i) {
            int a = acc[i];
            #pragma unroll
            for (int sw = 0; sw < 32; ++sw) a = __dp4a(pr[sw], vT[dbase + i][sw], a);
            acc[i] = a;
        }
        __syncthreads();
    }

    int pw[4];
    #pragma unroll
    for (int gq = 0; gq < 4; ++gq) {
        unsigned wd = 0;
        #pragma unroll
        for (int z = 0; z < 4; ++z) {
            int i = gq * 4 + z;
            float y = __fmul_rn(A_PV, (float)acc[i]);
            int q = (int)rintf(y);
            q = max(-128, min(127, q));
            wd |= ((unsigned)q & 255u) << (8 * z);
        }
        pw[gq] = (int)wd;
    }
    int4* dst = (int4*)&g_ao[(size_t)(b * T_ + t) * D_ + h * HD_ + sub * 16];
    *dst = make_int4(pw[0], pw[1], pw[2], pw[3]);
}

// ---------------- launch ----------------
extern "C" void kernel_launch(void* const* d_in, const int* in_sizes, int n_in,
                              void* d_out, int out_size)
{
    (void)n_in; (void)out_size;
    // Ordering detection from the size pattern:
    //   dict order:  [8388608(hs), 8388608(mask), 4194304, 2048, 4194304, 2048, 4194304, 2048, 4194304, 2048]
    //   alpha order: [4194304(Wk), 4194304(Wo), 4194304(Wq), 4194304(Wv), 8388608(mask), 2048(bk), 2048(bo), 2048(bq), 2048(bv), 8388608(hs)]
    int i_hs, i_Wq, i_bq, i_Wk, i_bk, i_Wv, i_bv, i_Wo, i_bo;
    if (in_sizes[0] == 4194304) {          // alphabetical
        i_Wk = 0; i_Wo = 1; i_Wq = 2; i_Wv = 3;
        i_bk = 5; i_bo = 6; i_bq = 7; i_bv = 8; i_hs = 9;
    } else {                                // dict / signature order
        i_hs = 0; i_Wq = 2; i_bq = 3; i_Wk = 4; i_bk = 5;
        i_Wv = 6; i_bv = 7; i_Wo = 8; i_bo = 9;
    }
    const float* bo = (const float*)d_in[i_bo];
    float* out = (float*)d_out;

    sniff_kernel<<<1, 256>>>(d_in[i_hs]);

    const int HSW = B_ * T_ * D_ / 4;   // 2097152 words
    const int WW  = D_ * D_ / 4;        // 1048576 words
    const int BW  = D_ / 4;             // 512 words
    pack_kernel<<<2048, 256>>>(d_in[i_hs], HSW, 0);
    pack_kernel<<<1024, 256>>>(d_in[i_Wq], WW, 1);
    pack_kernel<<<1024, 256>>>(d_in[i_Wk], WW, 2);
    pack_kernel<<<1024, 256>>>(d_in[i_Wv], WW, 3);
    pack_kernel<<<1024, 256>>>(d_in[i_Wo], WW, 4);
    pack_kernel<<<2, 256>>>(d_in[i_bq], BW, 5);
    pack_kernel<<<2, 256>>>(d_in[i_bk], BW, 6);
    pack_kernel<<<2, 256>>>(d_in[i_bv], BW, 7);

    dim3 gg(D_ / 64, (B_ * T_) / 64);   // (32, 64)
    gemm_i8_kernel<<<gg, 256>>>(nullptr, 3e-4f, nullptr, 0);
    gemm_i8_kernel<<<gg, 256>>>(nullptr, 3e-4f, nullptr, 1);
    gemm_i8_kernel<<<gg, 256>>>(nullptr, 3e-4f, nullptr, 2);
    attn_kernel<<<dim3(T_ / 64, B_ * H_), 256>>>();
    gemm_i8_kernel<<<gg, 256>>>(bo, 1e-4f, out, 3);
}

// round 3
// speedup vs baseline: 1.2545x; 1.2545x over previous
#include <cuda_runtime.h>
#include <cstdint>
#include <math.h>

#define B_  2
#define T_  2048
#define D_  2048
#define H_  32
#define HD_ 64
#define KW  (D_/4)   // 512 int words per D row

// ---------------- scratch (no allocation allowed) ----------------
static __device__ int g_mode;   // 0 = packed int8, 1 = int32-per-elem, 2 = float32-per-elem
static __device__ __align__(16) int8_t g_hs[B_*T_*D_];
static __device__ __align__(16) int8_t g_Wq[D_*D_];
static __device__ __align__(16) int8_t g_Wk[D_*D_];
static __device__ __align__(16) int8_t g_Wv[D_*D_];
static __device__ __align__(16) int8_t g_Wo[D_*D_];
static __device__ __align__(16) int8_t g_bq[D_];
static __device__ __align__(16) int8_t g_bk[D_];
static __device__ __align__(16) int8_t g_bv[D_];
static __device__ __align__(16) int8_t g_q [B_*T_*D_];
static __device__ __align__(16) int8_t g_k [B_*T_*D_];
static __device__ __align__(16) int8_t g_v [B_*T_*D_];
static __device__ __align__(16) int8_t g_ao[B_*T_*D_];

// ---------------- dtype sniff (unchanged, proven) ----------------
__global__ void sniff_kernel(const void* __restrict__ p)
{
    __shared__ int s_i32, s_f32;
    if (threadIdx.x == 0) { s_i32 = 1; s_f32 = 1; }
    __syncthreads();
    const int*   wi = (const int*)p;
    const float* wf = (const float*)p;
    int ok_i = 1, ok_f = 1;
    for (int i = threadIdx.x; i < 4096; i += blockDim.x) {
        int v = wi[i];
        if (v < -128 || v > 127) ok_i = 0;
        float f = wf[i];
        if (!(f >= -128.f && f <= 127.f && f == rintf(f))) ok_f = 0;
    }
    if (!ok_i) atomicExch(&s_i32, 0);
    if (!ok_f) atomicExch(&s_f32, 0);
    __syncthreads();
    if (threadIdx.x == 0) g_mode = s_i32 ? 1 : (s_f32 ? 2 : 0);
}

// ---------------- pack (unchanged, proven) ----------------
__global__ void pack_kernel(const void* __restrict__ in, int nwords, int sel)
{
    int8_t* outp =
        (sel == 0) ? g_hs : (sel == 1) ? g_Wq : (sel == 2) ? g_Wk :
        (sel == 3) ? g_Wv : (sel == 4) ? g_Wo : (sel == 5) ? g_bq :
        (sel == 6) ? g_bk : g_bv;
    int* ow = (int*)outp;
    const int mode = g_mode;
    int i = blockIdx.x * blockDim.x + threadIdx.x;
    const int stride = gridDim.x * blockDim.x;
    for (; i < nwords; i += stride) {
        int w;
        if (mode == 0) {
            w = ((const int*)in)[i];
        } else if (mode == 1) {
            int4 v = ((const int4*)in)[i];
            w = (v.x & 255) | ((v.y & 255) << 8) | ((v.z & 255) << 16) | ((v.w & 255) << 24);
        } else {
            float4 v = ((const float4*)in)[i];
            int a = (int)rintf(v.x) & 255, b = (int)rintf(v.y) & 255;
            int c = (int)rintf(v.z) & 255, d = (int)rintf(v.w) & 255;
            w = a | (b << 8) | (c << 16) | (d << 24);
        }
        ow[i] = w;
    }
}

// ---------------- int8 tensor-core mma ----------------
__device__ __forceinline__ void mma_s8(int& d0, int& d1, int& d2, int& d3,
                                       int a0, int a1, int a2, int a3,
                                       int b0, int b1)
{
    asm volatile(
        "mma.sync.aligned.m16n8k32.row.col.s32.s8.s8.s32 "
        "{%0,%1,%2,%3},{%4,%5,%6,%7},{%8,%9},{%0,%1,%2,%3};\n"
        : "+r"(d0), "+r"(d1), "+r"(d2), "+r"(d3)
        : "r"(a0), "r"(a1), "r"(a2), "r"(a3), "r"(b0), "r"(b1));
}

__device__ __forceinline__ void cp16(uint32_t dst, const void* src)
{
    asm volatile("cp.async.cg.shared.global [%0],[%1],16;\n" :: "r"(dst), "l"(src));
}
__device__ __forceinline__ void cp_commit() { asm volatile("cp.async.commit_group;\n"); }
__device__ __forceinline__ void cp_wait0()  { asm volatile("cp.async.wait_group 0;\n"); }

// ---------------- GEMM body: Y[m,n] = epi( sum_k X[m,k]*W[n,k] ) ----------------
// 128x128 block tile, 256 thr (8 warps, 2m x 4n), warp 64x32, BK=64 bytes.
// zsel 0/1/2: int8 out (q/k/v); zsel 3: fp32 out.
__device__ __forceinline__ void gemm_body(const float* __restrict__ bias_f,
                                          float alpha, float* __restrict__ outf,
                                          int zsel)
{
    __shared__ int As[2][128 * 20];
    __shared__ int Bs[2][128 * 20];

    const int tid = threadIdx.x, w = tid >> 5, lane = tid & 31;
    const int g = lane >> 2, tg = lane & 3;
    const int wm = w >> 2, wn = w & 3;
    const int m0 = blockIdx.y * 128, n0 = blockIdx.x * 128;

    const int4* X4 = (const int4*)((zsel == 3) ? (const void*)g_ao : (const void*)g_hs);
    const int4* W4 = (const int4*)((zsel == 0) ? (const void*)g_Wq :
                                   (zsel == 1) ? (const void*)g_Wk :
                                   (zsel == 2) ? (const void*)g_Wv : (const void*)g_Wo);

    const uint32_t asb = (uint32_t)__cvta_generic_to_shared(&As[0][0]);
    const uint32_t bsb = (uint32_t)__cvta_generic_to_shared(&Bs[0][0]);

    const int r_a = tid >> 2, c4_a = tid & 3;            // idx = tid (rows 0..63)
    const int r_b = (tid + 256) >> 2;                    // rows 64..127

    int acc[4][4][4];
    #pragma unroll
    for (int mt = 0; mt < 4; mt++)
        #pragma unroll
        for (int nt = 0; nt < 4; nt++)
            #pragma unroll
            for (int i = 0; i < 4; i++) acc[mt][nt][i] = 0;

    // issue stage kt into buffer buf
    auto issue = [&](int kt, int buf) {
        uint32_t ab = asb + (uint32_t)buf * 128 * 20 * 4;
        uint32_t bb = bsb + (uint32_t)buf * 128 * 20 * 4;
        cp16(ab + (uint32_t)(r_a * 20 + c4_a * 4) * 4, X4 + (size_t)(m0 + r_a) * 128 + kt * 4 + c4_a);
        cp16(ab + (uint32_t)(r_b * 20 + c4_a * 4) * 4, X4 + (size_t)(m0 + r_b) * 128 + kt * 4 + c4_a);
        cp16(bb + (uint32_t)(r_a * 20 + c4_a * 4) * 4, W4 + (size_t)(n0 + r_a) * 128 + kt * 4 + c4_a);
        cp16(bb + (uint32_t)(r_b * 20 + c4_a * 4) * 4, W4 + (size_t)(n0 + r_b) * 128 + kt * 4 + c4_a);
        cp_commit();
    };

    issue(0, 0);
    for (int kt = 0; kt < 32; ++kt) {
        cp_wait0();
        __syncthreads();
        if (kt < 31) issue(kt + 1, (kt + 1) & 1);
        const int* A = As[kt & 1];
        const int* Bb = Bs[kt & 1];
        #pragma unroll
        for (int ks = 0; ks < 2; ++ks) {
            int a[4][4];
            #pragma unroll
            for (int mt = 0; mt < 4; mt++) {
                int r = wm * 64 + mt * 16 + g;
                a[mt][0] = A[r * 20 + ks * 8 + tg];
                a[mt][1] = A[(r + 8) * 20 + ks * 8 + tg];
                a[mt][2] = A[r * 20 + ks * 8 + 4 + tg];
                a[mt][3] = A[(r + 8) * 20 + ks * 8 + 4 + tg];
            }
            #pragma unroll
            for (int nt = 0; nt < 4; nt++) {
                int bc = wn * 32 + nt * 8 + g;
                int b0 = Bb[bc * 20 + ks * 8 + tg];
                int b1 = Bb[bc * 20 + ks * 8 + 4 + tg];
                #pragma unroll
                for (int mt = 0; mt < 4; mt++)
                    mma_s8(acc[mt][nt][0], acc[mt][nt][1], acc[mt][nt][2], acc[mt][nt][3],
                           a[mt][0], a[mt][1], a[mt][2], a[mt][3], b0, b1);
            }
        }
    }

    // epilogue
    if (zsel < 3) {
        const int8_t* bi = (zsel == 0) ? g_bq : (zsel == 1) ? g_bk : g_bv;
        int8_t* Y = (zsel == 0) ? g_q : (zsel == 1) ? g_k : g_v;
        #pragma unroll
        for (int nt = 0; nt < 4; nt++) {
            int col = n0 + wn * 32 + nt * 8 + 2 * tg;
            float bb0 = (float)bi[col], bb1 = (float)bi[col + 1];
            #pragma unroll
            for (int mt = 0; mt < 4; mt++) {
                int r = m0 + wm * 64 + mt * 16 + g;
                #pragma unroll
                for (int half = 0; half < 2; half++) {
                    int rr = r + half * 8;
                    float y0 = __fadd_rn(__fmul_rn(alpha, (float)acc[mt][nt][half * 2 + 0]), bb0);
                    float y1 = __fadd_rn(__fmul_rn(alpha, (float)acc[mt][nt][half * 2 + 1]), bb1);
                    int q0 = max(-128, min(127, (int)rintf(y0)));
                    int q1 = max(-128, min(127, (int)rintf(y1)));
                    *(short*)&Y[(size_t)rr * D_ + col] = (short)((q0 & 255) | ((q1 & 255) << 8));
                }
            }
        }
    } else {
        #pragma unroll
        for (int nt = 0; nt < 4; nt++) {
            int col = n0 + wn * 32 + nt * 8 + 2 * tg;
            float bb0 = bias_f[col], bb1 = bias_f[col + 1];
            #pragma unroll
            for (int mt = 0; mt < 4; mt++) {
                int r = m0 + wm * 64 + mt * 16 + g;
                #pragma unroll
                for (int half = 0; half < 2; half++) {
                    int rr = r + half * 8;
                    float y0 = __fadd_rn(__fmul_rn(alpha, (float)acc[mt][nt][half * 2 + 0]), bb0);
                    float y1 = __fadd_rn(__fmul_rn(alpha, (float)acc[mt][nt][half * 2 + 1]), bb1);
                    *(float2*)&outf[(size_t)rr * D_ + col] = make_float2(y0, y1);
                }
            }
        }
    }
}

__global__ __launch_bounds__(256, 2) void gemm_qkv_kernel()
{
    gemm_body(nullptr, 3e-4f, nullptr, (int)blockIdx.z);
}
__global__ __launch_bounds__(256, 2) void gemm_out_kernel(const float* __restrict__ bo,
                                                          float* __restrict__ out)
{
    gemm_body(bo, 1e-4f, out, 3);
}

// ---------------- fused attention (tensor-core QK / PV) ----------------
// Block: 64 q-rows x one (b,h). 256 thr, 8 warps.
// QK: warp (wm = w&3 -> 16 rows, wn = w>>2 -> 64-col slab), 8 n-tiles.
// PV: warp (wm rows, wn -> 32-col slab), 4 n-tiles, 4 k-steps.
__global__ __launch_bounds__(256, 1) void attn_kernel()
{
    const float A_QK = 2e-5f, A_PV = 1e-2f;
    const int bh = blockIdx.y, b = bh >> 5, h = bh & 31;
    const int r0 = blockIdx.x * 64;
    const int tid = threadIdx.x, w = tid >> 5, lane = tid & 31;
    const int g = lane >> 2, tg = lane & 3;
    const int wm = w & 3, wn = w >> 2;

    __shared__ int   qs[64 * 20];
    __shared__ int   ks[128 * 20];
    __shared__ int   vraw[128 * 20];
    __shared__ int   vT[64 * 36];
    __shared__ int   ps[64 * 36];
    __shared__ float redm[2][64], redl[2][64];
    __shared__ float rowM[64], rowRL[64];

    const int4* Q4 = (const int4*)g_q;
    const int4* K4 = (const int4*)g_k;
    const int4* V4 = (const int4*)g_v;

    // load q tile (64 rows x 16 words)
    {
        int row = tid >> 2, c4 = tid & 3;
        *(int4*)&qs[row * 20 + c4 * 4] = Q4[(size_t)(b * T_ + r0 + row) * 128 + h * 4 + c4];
    }

    const int nch = ((r0 + 63) >> 7) + 1;
    const int tA = r0 + wm * 16 + g, tB = tA + 8;

    // ---------- pass A: online row stats ----------
    float mA = -1e30f, lA = 0.f, mB = -1e30f, lB = 0.f;
    for (int c = 0; c < nch; ++c) {
        const int s0 = c << 7;
        {
            int idx0 = tid, idx1 = tid + 256;
            int ra = idx0 >> 2, ca = idx0 & 3, rb = idx1 >> 2;
            *(int4*)&ks[ra * 20 + ca * 4] = K4[(size_t)(b * T_ + s0 + ra) * 128 + h * 4 + ca];
            *(int4*)&ks[rb * 20 + ca * 4] = K4[(size_t)(b * T_ + s0 + rb) * 128 + h * 4 + ca];
        }
        __syncthreads();

        int cc[8][4];
        #pragma unroll
        for (int nt = 0; nt < 8; nt++)
            #pragma unroll
            for (int i = 0; i < 4; i++) cc[nt][i] = 0;
        #pragma unroll
        for (int ksi = 0; ksi < 2; ++ksi) {
            int r = wm * 16 + g;
            int a0 = qs[r * 20 + ksi * 8 + tg];
            int a1 = qs[(r + 8) * 20 + ksi * 8 + tg];
            int a2 = qs[r * 20 + ksi * 8 + 4 + tg];
            int a3 = qs[(r + 8) * 20 + ksi * 8 + 4 + tg];
            #pragma unroll
            for (int nt = 0; nt < 8; nt++) {
                int bc = wn * 64 + nt * 8 + g;
                int b0 = ks[bc * 20 + ksi * 8 + tg];
                int b1 = ks[bc * 20 + ksi * 8 + 4 + tg];
                mma_s8(cc[nt][0], cc[nt][1], cc[nt][2], cc[nt][3], a0, a1, a2, a3, b0, b1);
            }
        }
        #pragma unroll
        for (int nt = 0; nt < 8; nt++) {
            int scol = s0 + wn * 64 + nt * 8 + 2 * tg;
            #pragma unroll
            for (int e = 0; e < 2; e++) {
                int s = scol + e;
                if (s <= tA) {
                    float sc = __fmul_rn(A_QK, (float)cc[nt][e]);
                    float mn = fmaxf(mA, sc);
                    lA = lA * __expf(mA - mn) + __expf(sc - mn);
                    mA = mn;
                }
                if (s <= tB) {
                    float sc = __fmul_rn(A_QK, (float)cc[nt][2 + e]);
                    float mn = fmaxf(mB, sc);
                    lB = lB * __expf(mB - mn) + __expf(sc - mn);
                    mB = mn;
                }
            }
        }
        __syncthreads();
    }
    // merge across tg lanes
    #pragma unroll
    for (int d = 1; d < 4; d <<= 1) {
        float mo = __shfl_xor_sync(0xffffffffu, mA, d);
        float lo = __shfl_xor_sync(0xffffffffu, lA, d);
        float mn = fmaxf(mA, mo);
        lA = lA * __expf(mA - mn) + lo * __expf(mo - mn); mA = mn;
        mo = __shfl_xor_sync(0xffffffffu, mB, d);
        lo = __shfl_xor_sync(0xffffffffu, lB, d);
        mn = fmaxf(mB, mo);
        lB = lB * __expf(mB - mn) + lo * __expf(mo - mn); mB = mn;
    }
    if (tg == 0) {
        redm[wn][wm * 16 + g] = mA;     redl[wn][wm * 16 + g] = lA;
        redm[wn][wm * 16 + g + 8] = mB; redl[wn][wm * 16 + g + 8] = lB;
    }
    __syncthreads();
    if (tid < 64) {
        float m0 = redm[0][tid], m1 = redm[1][tid];
        float l0 = redl[0][tid], l1 = redl[1][tid];
        float M = fmaxf(m0, m1);
        float L = l0 * __expf(m0 - M) + l1 * __expf(m1 - M);
        rowM[tid] = M;
        rowRL[tid] = 127.0f / L;
    }
    __syncthreads();

    const float MA = rowM[wm * 16 + g],     RA = rowRL[wm * 16 + g];
    const float MB = rowM[wm * 16 + g + 8], RB = rowRL[wm * 16 + g + 8];

    // ---------- pass B: recompute scores, quantize p, PV ----------
    int oacc[4][4];
    #pragma unroll
    for (int nt = 0; nt < 4; nt++)
        #pragma unroll
        for (int i = 0; i < 4; i++) oacc[nt][i] = 0;

    for (int c = 0; c < nch; ++c) {
        const int s0 = c << 7;
        {
            int idx0 = tid, idx1 = tid + 256;
            int ra = idx0 >> 2, ca = idx0 & 3, rb = idx1 >> 2;
            size_t base_a = (size_t)(b * T_ + s0 + ra) * 128 + h * 4 + ca;
            size_t base_b = (size_t)(b * T_ + s0 + rb) * 128 + h * 4 + ca;
            *(int4*)&ks[ra * 20 + ca * 4]   = K4[base_a];
            *(int4*)&ks[rb * 20 + ca * 4]   = K4[base_b];
            *(int4*)&vraw[ra * 20 + ca * 4] = V4[base_a];
            *(int4*)&vraw[rb * 20 + ca * 4] = V4[base_b];
        }
        __syncthreads();   // also protects ps/vT from previous iteration's PV reads

        int cc[8][4];
        #pragma unroll
        for (int nt = 0; nt < 8; nt++)
            #pragma unroll
            for (int i = 0; i < 4; i++) cc[nt][i] = 0;
        #pragma unroll
        for (int ksi = 0; ksi < 2; ++ksi) {
            int r = wm * 16 + g;
            int a0 = qs[r * 20 + ksi * 8 + tg];
            int a1 = qs[(r + 8) * 20 + ksi * 8 + tg];
            int a2 = qs[r * 20 + ksi * 8 + 4 + tg];
            int a3 = qs[(r + 8) * 20 + ksi * 8 + 4 + tg];
            #pragma unroll
            for (int nt = 0; nt < 8; nt++) {
                int bc = wn * 64 + nt * 8 + g;
                int b0 = ks[bc * 20 + ksi * 8 + tg];
                int b1 = ks[bc * 20 + ksi * 8 + 4 + tg];
                mma_s8(cc[nt][0], cc[nt][1], cc[nt][2], cc[nt][3], a0, a1, a2, a3, b0, b1);
            }
        }
        // quantize p -> ps (byte layout: row*144 + s_local)
        char* psb = (char*)ps;
        #pragma unroll
        for (int nt = 0; nt < 8; nt++) {
            int col = wn * 64 + nt * 8 + 2 * tg;
            int scol = s0 + col;
            int pA0 = 0, pA1 = 0, pB0 = 0, pB1 = 0;
            if (scol <= tA) {
                float p = __expf(__fmul_rn(A_QK, (float)cc[nt][0]) - MA) * RA;
                pA0 = min(127, (int)rintf(p));
            }
            if (scol + 1 <= tA) {
                float p = __expf(__fmul_rn(A_QK, (float)cc[nt][1]) - MA) * RA;
                pA1 = min(127, (int)rintf(p));
            }
            if (scol <= tB) {
                float p = __expf(__fmul_rn(A_QK, (float)cc[nt][2]) - MB) * RB;
                pB0 = min(127, (int)rintf(p));
            }
            if (scol + 1 <= tB) {
                float p = __expf(__fmul_rn(A_QK, (float)cc[nt][3]) - MB) * RB;
                pB1 = min(127, (int)rintf(p));
            }
            *(short*)(psb + (wm * 16 + g) * 144 + col)     = (short)(pA0 | (pA1 << 8));
            *(short*)(psb + (wm * 16 + g + 8) * 144 + col) = (short)(pB0 | (pB1 << 8));
        }
        // build vT[d][sw]: packed v[s0+4sw+z][d]
        #pragma unroll
        for (int k = 0; k < 8; ++k) {
            int idx = k * 256 + tid;
            int d = idx >> 5, sw = idx & 31;
            int cword = d >> 2, csh = (d & 3) * 8;
            unsigned wd = 0;
            #pragma unroll
            for (int z = 0; z < 4; ++z) {
                unsigned by = ((unsigned)vraw[(4 * sw + z) * 20 + cword] >> csh) & 255u;
                wd |= by << (8 * z);
            }
            vT[d * 36 + sw] = (int)wd;
        }
        __syncthreads();

        // PV mma: rows wm*16..+15, cols wn*32..+31, k = 128 (4 k-steps)
        #pragma unroll
        for (int kk = 0; kk < 4; ++kk) {
            int r = wm * 16 + g;
            int a0 = ps[r * 36 + kk * 8 + tg];
            int a1 = ps[(r + 8) * 36 + kk * 8 + tg];
            int a2 = ps[r * 36 + kk * 8 + 4 + tg];
            int a3 = ps[(r + 8) * 36 + kk * 8 + 4 + tg];
            #pragma unroll
            for (int nt = 0; nt < 4; nt++) {
                int dc = wn * 32 + nt * 8 + g;
                int b0 = vT[dc * 36 + kk * 8 + tg];
                int b1 = vT[dc * 36 + kk * 8 + 4 + tg];
                mma_s8(oacc[nt][0], oacc[nt][1], oacc[nt][2], oacc[nt][3],
                       a0, a1, a2, a3, b0, b1);
            }
        }
        __syncthreads();
    }

    // epilogue: int8 = clip(rint(A_PV * pv))
    #pragma unroll
    for (int nt = 0; nt < 4; nt++) {
        int col = h * HD_ + wn * 32 + nt * 8 + 2 * tg;
        float yA0 = __fmul_rn(A_PV, (float)oacc[nt][0]);
        float yA1 = __fmul_rn(A_PV, (float)oacc[nt][1]);
        float yB0 = __fmul_rn(A_PV, (float)oacc[nt][2]);
        float yB1 = __fmul_rn(A_PV, (float)oacc[nt][3]);
        int qA0 = max(-128, min(127, (int)rintf(yA0)));
        int qA1 = max(-128, min(127, (int)rintf(yA1)));
        int qB0 = max(-128, min(127, (int)rintf(yB0)));
        int qB1 = max(-128, min(127, (int)rintf(yB1)));
        *(short*)&g_ao[(size_t)(b * T_ + tA) * D_ + col] = (short)((qA0 & 255) | ((qA1 & 255) << 8));
        *(short*)&g_ao[(size_t)(b * T_ + tB) * D_ + col] = (short)((qB0 & 255) | ((qB1 & 255) << 8));
    }
}

// ---------------- launch ----------------
extern "C" void kernel_launch(void* const* d_in, const int* in_sizes, int n_in,
                              void* d_out, int out_size)
{
    (void)n_in; (void)out_size;
    int i_hs, i_Wq, i_bq, i_Wk, i_bk, i_Wv, i_bv, i_Wo, i_bo;
    if (in_sizes[0] == 4194304) {          // alphabetical
        i_Wk = 0; i_Wo = 1; i_Wq = 2; i_Wv = 3;
        i_bk = 5; i_bo = 6; i_bq = 7; i_bv = 8; i_hs = 9;
    } else {                                // dict / signature order
        i_hs = 0; i_Wq = 2; i_bq = 3; i_Wk = 4; i_bk = 5;
        i_Wv = 6; i_bv = 7; i_Wo = 8; i_bo = 9;
    }
    const float* bo = (const float*)d_in[i_bo];
    float* out = (float*)d_out;

    sniff_kernel<<<1, 256>>>(d_in[i_hs]);

    const int HSW = B_ * T_ * D_ / 4;
    const int WW  = D_ * D_ / 4;
    const int BW  = D_ / 4;
    pack_kernel<<<2048, 256>>>(d_in[i_hs], HSW, 0);
    pack_kernel<<<1024, 256>>>(d_in[i_Wq], WW, 1);
    pack_kernel<<<1024, 256>>>(d_in[i_Wk], WW, 2);
    pack_kernel<<<1024, 256>>>(d_in[i_Wv], WW, 3);
    pack_kernel<<<1024, 256>>>(d_in[i_Wo], WW, 4);
    pack_kernel<<<2, 256>>>(d_in[i_bq], BW, 5);
    pack_kernel<<<2, 256>>>(d_in[i_bk], BW, 6);
    pack_kernel<<<2, 256>>>(d_in[i_bv], BW, 7);

    gemm_qkv_kernel<<<dim3(D_ / 128, (B_ * T_) / 128, 3), 256>>>();
    attn_kernel<<<dim3(T_ / 64, B_ * H_), 256>>>();
    gemm_out_kernel<<<dim3(D_ / 128, (B_ * T_) / 128), 256>>>(bo, out);
}